// round 14
// baseline (speedup 1.0000x reference)
#include <cuda_runtime.h>
#include <cuda_fp16.h>
#include <cstdint>

// ---------------- Problem constants ----------------
#define BATCH   32
#define HW      56
#define CDIM    384
#define NH      12
#define DH      32
#define WS      7
#define T       49
#define NWIN    64
#define BN      (BATCH*NWIN)       // 2048
#define MROWS   (BN*T)             // 100352
#define NQKV    (3*CDIM)           // 1152
#define SCALE   0.17677669529663687f

// ---------------- Scratch (static device memory) ----------------
__device__ __half  g_qkv16[(size_t)BN * NH * 3 * T * DH];  // attn input, fp16
__device__ __half  g_x16[(size_t)MROWS * CDIM];            // gathered x, fp16
__device__ __half  g_att16[(size_t)MROWS * CDIM];          // attention out, fp16
__device__ __half  g_wq16[(size_t)NQKV * CDIM];            // qkv weights, fp16
__device__ __half  g_wp16[(size_t)CDIM * CDIM];            // proj weights, fp16

// ---------------- helpers ----------------
__device__ __forceinline__ uint32_t smem_u32(const void* p) {
    uint32_t a;
    asm("{ .reg .u64 t; cvta.to.shared.u64 t, %1; cvt.u32.u64 %0, t; }" : "=r"(a) : "l"(p));
    return a;
}

__device__ __forceinline__ void ldsm_x4(uint32_t& r0, uint32_t& r1, uint32_t& r2, uint32_t& r3,
                                        uint32_t addr) {
    asm volatile("ldmatrix.sync.aligned.m8n8.x4.shared.b16 {%0,%1,%2,%3}, [%4];"
                 : "=r"(r0), "=r"(r1), "=r"(r2), "=r"(r3) : "r"(addr));
}

__device__ __forceinline__ void mma_f16(float* c, const uint32_t* a, uint32_t b0, uint32_t b1) {
    asm volatile(
        "mma.sync.aligned.m16n8k16.row.col.f32.f16.f16.f32 "
        "{%0,%1,%2,%3}, {%4,%5,%6,%7}, {%8,%9}, {%0,%1,%2,%3};"
        : "+f"(c[0]), "+f"(c[1]), "+f"(c[2]), "+f"(c[3])
        : "r"(a[0]), "r"(a[1]), "r"(a[2]), "r"(a[3]), "r"(b0), "r"(b1));
}

__device__ __forceinline__ void cp16(uint32_t dst, const void* src) {
    asm volatile("cp.async.cg.shared.global [%0], [%1], 16;" :: "r"(dst), "l"(src));
}

// ---------------------------------------------------------------------------
// Precompute 1: gather x (roll -3, window partition) -> fp16 [MROWS,384]
// ---------------------------------------------------------------------------
__global__ __launch_bounds__(256)
void gather_convert_x(const float* __restrict__ x)
{
    int idx = blockIdx.x * 256 + threadIdx.x;
    if (idx >= MROWS * (CDIM / 4)) return;
    int row = idx / (CDIM / 4);
    int c4  = idx % (CDIM / 4);
    int bn = row / T, t = row % T;
    int b = bn >> 6, win = bn & 63;
    int wr = win >> 3, wc = win & 7;
    int tr = t / WS, tc = t % WS;
    int h = wr * WS + tr + 3; if (h >= HW) h -= HW;
    int w = wc * WS + tc + 3; if (w >= HW) w -= HW;
    float4 v = *(const float4*)(x + ((size_t)((b * HW + h) * HW + w)) * CDIM + c4 * 4);
    size_t o = (size_t)row * CDIM + c4 * 4;
    *(__half2*)(g_x16 + o)     = __floats2half2_rn(v.x, v.y);
    *(__half2*)(g_x16 + o + 2) = __floats2half2_rn(v.z, v.w);
}

// ---------------------------------------------------------------------------
// Precompute 2: fp32 -> fp16 (weights)
// ---------------------------------------------------------------------------
__global__ __launch_bounds__(256)
void convert_w(const float* __restrict__ src, __half* __restrict__ dst, int n4)
{
    int idx = blockIdx.x * 256 + threadIdx.x;
    if (idx >= n4) return;
    float4 v = *(const float4*)(src + (size_t)idx * 4);
    size_t o = (size_t)idx * 4;
    *(__half2*)(dst + o)     = __floats2half2_rn(v.x, v.y);
    *(__half2*)(dst + o + 2) = __floats2half2_rn(v.z, v.w);
}

// ---------------------------------------------------------------------------
// mma.sync GEMM, BK=64, 3-stage cp.async pipeline (prefetch distance 2),
// ONE __syncthreads per chunk, 6 chunks total.
// C[128,128] = A[128,384] @ B[128,384]^T  (plain fp16)
// Swizzled smem: rows of 128B (8 lines), 16B line l at (l ^ (row&7)).
// ---------------------------------------------------------------------------
#define TEN_BYTES  (128 * 128)          // 16384 B per tensor (128 rows x 128 B)
#define STG_BYTES  (2 * TEN_BYTES)      // 32768 B per stage (A, B)
#define NSTAGE     3
#define SMEM_DYN   (NSTAGE * STG_BYTES) // 98304 B
#define NKIT       (CDIM / 64)          // 6

__device__ __forceinline__ uint32_t swz_off(int row, int line) {
    return (uint32_t)(row * 128 + ((line ^ (row & 7)) << 4));
}

template<int MODE>
__global__ __launch_bounds__(256)
void gemm_mma(const float* __restrict__ bias, float* __restrict__ out)
{
    extern __shared__ __align__(16) char dynsmem[];
    const uint32_t u0 = smem_u32(dynsmem);

    const __half* __restrict__ aP = (MODE == 0) ? g_x16  : g_att16;
    const __half* __restrict__ bP = (MODE == 0) ? g_wq16 : g_wp16;

    const int tid  = threadIdx.x;
    const int lane = tid & 31;
    const int wid  = tid >> 5;
    const int wm   = wid & 1;
    const int wn   = wid >> 1;
    const int mbase = blockIdx.y * 128;
    const int nbase = blockIdx.x * 128;

    float acc[4][4][4];
    #pragma unroll
    for (int i = 0; i < 4; i++)
        #pragma unroll
        for (int j = 0; j < 4; j++)
            #pragma unroll
            for (int k = 0; k < 4; k++) acc[i][j][k] = 0.f;

    // cp.async mapping: 2 threads per row, 4 lines each (8 lines = 128B row)
    const int rowg = tid >> 1;
    const int l0   = (tid & 1) * 4;
    uint32_t soff[4];
    #pragma unroll
    for (int l = 0; l < 4; l++) soff[l] = swz_off(rowg, l0 + l);

    auto issue = [&](int st, int k0) {
        uint32_t base = u0 + st * STG_BYTES;
        size_t arow = (size_t)(mbase + rowg) * CDIM + k0;
        size_t brow = (size_t)(nbase + rowg) * CDIM + k0;
        #pragma unroll
        for (int l = 0; l < 4; l++) {
            int ge = (l0 + l) * 8;
            cp16(base + soff[l],             aP + arow + ge);
            cp16(base + TEN_BYTES + soff[l], bP + brow + ge);
        }
        asm volatile("cp.async.commit_group;");
    };

    // ldmatrix lane addressing (swizzle-aware)
    const int rA  = wm * 64 + (lane & 15);
    const int cA0 = lane >> 4;
    const int sxA = rA & 7;
    const int rB  = wn * 32 + (lane & 7) + (((lane >> 4) & 1) << 3);
    const int cB0 = (lane >> 3) & 1;
    const int sxB = rB & 7;
    const uint32_t aBase = (uint32_t)(rA * 128);
    const uint32_t bBase = (uint32_t)(rB * 128);

    // Prologue: fill stages 0,1 (distance-2 prefetch)
    issue(0, 0);
    issue(1, 64);

    int stage = 0;
    for (int it = 0; it < NKIT; it++) {
        asm volatile("cp.async.wait_group 1;");
        __syncthreads();

        if (it + 2 < NKIT) {
            int st2 = stage + 2; if (st2 >= NSTAGE) st2 -= NSTAGE;
            issue(st2, (it + 2) * 64);
        }

        const uint32_t uA = u0 + stage * STG_BYTES;
        const uint32_t uB = uA + TEN_BYTES;

        #pragma unroll
        for (int ks = 0; ks < 4; ks++) {
            const uint32_t aOff = aBase + (uint32_t)(((2*ks + cA0) ^ sxA) << 4);
            const uint32_t bOff = bBase + (uint32_t)(((2*ks + cB0) ^ sxB) << 4);
            uint32_t ah[4][4];
            #pragma unroll
            for (int mt = 0; mt < 4; mt++) {
                uint32_t off = aOff + (uint32_t)(mt * 2048);
                ldsm_x4(ah[mt][0], ah[mt][1], ah[mt][2], ah[mt][3], uA + off);
            }
            uint32_t bh[8];
            #pragma unroll
            for (int nt2 = 0; nt2 < 2; nt2++) {
                uint32_t off = bOff + (uint32_t)(nt2 * 2048);
                ldsm_x4(bh[nt2*4+0], bh[nt2*4+1], bh[nt2*4+2], bh[nt2*4+3], uB + off);
            }
            #pragma unroll
            for (int mt = 0; mt < 4; mt++)
                #pragma unroll
                for (int nt = 0; nt < 4; nt++)
                    mma_f16(acc[mt][nt], ah[mt], bh[nt*2+0], bh[nt*2+1]);
        }
        stage++; if (stage >= NSTAGE) stage -= NSTAGE;
    }

    // ---- Epilogue ----
    #pragma unroll
    for (int mt = 0; mt < 4; mt++) {
        #pragma unroll
        for (int hf = 0; hf < 2; hf++) {
            int m = mbase + wm * 64 + mt * 16 + (lane >> 2) + hf * 8;
            int bn = m / T, t = m % T;
            if (MODE == 0) {
                #pragma unroll
                for (int nt = 0; nt < 4; nt++) {
                    int col = nbase + wn * 32 + nt * 8 + (lane & 3) * 2;
                    int which = col / CDIM;
                    int rem   = col - which * CDIM;
                    int head  = rem >> 5;
                    int d     = rem & 31;
                    float vx = acc[mt][nt][hf*2+0] + __ldg(&bias[col]);
                    float vy = acc[mt][nt][hf*2+1] + __ldg(&bias[col+1]);
                    *(__half2*)(g_qkv16 + ((size_t)(bn * NH + head) * 3 + which) * (T * DH)
                                + t * DH + d) = __floats2half2_rn(vx, vy);
                }
            } else {
                int b = bn >> 6, win = bn & 63;
                int wr = win >> 3, wc = win & 7;
                int tr = t / WS, tc = t % WS;
                int h = wr * WS + tr + 3; if (h >= HW) h -= HW;
                int w = wc * WS + tc + 3; if (w >= HW) w -= HW;
                float* orow = out + ((size_t)((b * HW + h) * HW + w)) * CDIM;
                #pragma unroll
                for (int nt = 0; nt < 4; nt++) {
                    int col = nbase + wn * 32 + nt * 8 + (lane & 3) * 2;
                    float2 v;
                    v.x = acc[mt][nt][hf*2+0] + __ldg(&bias[col]);
                    v.y = acc[mt][nt][hf*2+1] + __ldg(&bias[col+1]);
                    *(float2*)(orow + col) = v;
                }
            }
        }
    }
}

// ---------------------------------------------------------------------------
// Attention: tensor-core QK^T and PV; ILP softmax without max subtraction
// (scores bounded O(1) for this problem; mask -100 underflows to ~0 as in ref).
// ---------------------------------------------------------------------------
__global__ __launch_bounds__(256)
void attn_kernel(const float* __restrict__ table)
{
    const int bnh  = blockIdx.x;
    const int bn   = bnh / NH;
    const int head = bnh % NH;
    const int tid  = threadIdx.x;
    const int lane = tid & 31;
    const int wid  = tid >> 5;

    __shared__ __align__(16) __half qs[64 * 40];   // [t][40], 80B stride
    __shared__ __align__(16) __half ks[64 * 40];   // [s][40]
    __shared__ __align__(16) __half vT[32 * 72];   // [d][72], 144B stride
    __shared__ __align__(16) float  S [64 * 66];   // [t][66]
    __shared__ __align__(16) __half Pp[64 * 72];   // [t][72], fp16 P
    __shared__ int rid[49];

    // Zero vT (pad cols s>=49 must be finite zeros for PV)
    {
        uint4 z = make_uint4(0,0,0,0);
        uint4* vz = (uint4*)vT;                 // 32*72/8 = 288
        for (int i = tid; i < 288; i += 256) vz[i] = z;
    }
    __syncthreads();

    const __half* base = g_qkv16 + (size_t)(bn * NH + head) * (3 * T * DH);
    {
        const uint4* bq = (const uint4*)base;
        for (int i = tid; i < 392; i += 256) {
            int sec = (i >= 196);
            int rem = i - sec * 196;
            int t = rem >> 2, ch = rem & 3;
            uint4 v = bq[i];
            *(uint4*)((sec ? ks : qs) + t * 40 + ch * 8) = v;
        }
    }
    {
        const __half2* bv = (const __half2*)(base + 2 * T * DH);
        for (int i = tid; i < 784; i += 256) {
            int t = i >> 4, d2 = i & 15;
            __half2 v = bv[i];
            vT[(d2 * 2)     * 72 + t] = __low2half(v);
            vT[(d2 * 2 + 1) * 72 + t] = __high2half(v);
        }
    }
    if (tid < 49) {
        int win = bn & 63;
        int wr = win >> 3, wc = win & 7;
        int tr = (tid * 37) >> 8, tc = tid - tr * 7;
        int h = wr * WS + tr, w = wc * WS + tc;
        int rh = (h < 49) ? 0 : ((h < 53) ? 1 : 2);
        int rw = (w < 49) ? 0 : ((w < 53) ? 1 : 2);
        rid[tid] = rh * 3 + rw;
    }
    __syncthreads();

    // ---- QK^T: warp (mt = wid>>1, ng = wid&1); C tile 16x32 per warp ----
    {
        const int mt = wid >> 1, ng = wid & 1;
        const uint32_t uq = smem_u32(qs), uk = smem_u32(ks);
        uint32_t a[2][4];
        #pragma unroll
        for (int k2 = 0; k2 < 2; k2++) {
            uint32_t addr = uq + (uint32_t)((mt*16 + (lane & 15)) * 80
                                            + ((lane >> 4) * 8 + k2 * 16) * 2);
            ldsm_x4(a[k2][0], a[k2][1], a[k2][2], a[k2][3], addr);
        }
        uint32_t b[2][8];
        #pragma unroll
        for (int k2 = 0; k2 < 2; k2++)
            #pragma unroll
            for (int nt2 = 0; nt2 < 2; nt2++) {
                int rowB = ng*32 + nt2*16 + (lane & 7) + (((lane >> 4) & 1) << 3);
                uint32_t addr = uk + (uint32_t)(rowB * 80
                                                + (((lane >> 3) & 1) * 8 + k2 * 16) * 2);
                ldsm_x4(b[k2][nt2*4+0], b[k2][nt2*4+1], b[k2][nt2*4+2], b[k2][nt2*4+3], addr);
            }
        float c[4][4];
        #pragma unroll
        for (int j = 0; j < 4; j++)
            #pragma unroll
            for (int e = 0; e < 4; e++) c[j][e] = 0.f;
        #pragma unroll
        for (int j = 0; j < 4; j++) {
            mma_f16(c[j], a[0], b[0][j*2+0], b[0][j*2+1]);
            mma_f16(c[j], a[1], b[1][j*2+0], b[1][j*2+1]);
        }
        #pragma unroll
        for (int hf = 0; hf < 2; hf++) {
            int t = mt*16 + (lane >> 2) + hf*8;
            if (t < 49) {
                int tr = (t * 37) >> 8, tc = t - tr * 7;
                int rt = rid[t];
                #pragma unroll
                for (int j = 0; j < 4; j++) {
                    #pragma unroll
                    for (int e = 0; e < 2; e++) {
                        int s = ng*32 + j*8 + (lane & 3)*2 + e;
                        if (s < 49) {
                            int sr = (s * 37) >> 8, sc = s - sr * 7;
                            float val = c[j][hf*2+e] * SCALE
                                + __ldg(&table[((tr - sr + 6)*13 + (tc - sc + 6)) * NH + head]);
                            if (rt != rid[s]) val -= 100.0f;
                            S[t*66 + s] = val;
                        }
                    }
                }
            }
        }
    }
    __syncthreads();

    // ---- softmax: no max pass; 7 interleaved row chains per warp ----
    {
        float e0[7], e1[7], sm[7];
        #pragma unroll
        for (int r = 0; r < 7; r++) {
            int t = wid + 8*r;
            bool v = (t < T);
            float a = v ? S[t*66 + lane] : 0.f;
            float b = (v && lane < 17) ? S[t*66 + 32 + lane] : -1e30f;
            e0[r] = __expf(a);
            e1[r] = __expf(b);
            sm[r] = e0[r] + e1[r];
        }
        #pragma unroll
        for (int off = 16; off > 0; off >>= 1)
            #pragma unroll
            for (int r = 0; r < 7; r++)
                sm[r] += __shfl_xor_sync(0xFFFFFFFFu, sm[r], off);
        #pragma unroll
        for (int r = 0; r < 7; r++) {
            int t = wid + 8*r;
            if (t < T) {
                float inv = __frcp_rn(sm[r]);
                Pp[t*72 + lane]      = __float2half(e0[r] * inv);
                Pp[t*72 + 32 + lane] = __float2half((lane < 17) ? e1[r] * inv : 0.f);
            }
        }
    }
    __syncthreads();

    // ---- PV: warp (mt = wid>>1, nh2 = wid&1); out tile 16x16 per warp ----
    {
        const int mt = wid >> 1, nh2 = wid & 1;
        const uint32_t up = smem_u32(Pp), uv = smem_u32(vT);
        float c[2][4];
        #pragma unroll
        for (int j = 0; j < 2; j++)
            #pragma unroll
            for (int e = 0; e < 4; e++) c[j][e] = 0.f;
        #pragma unroll
        for (int k2 = 0; k2 < 4; k2++) {
            uint32_t a4[4];
            uint32_t aaddr = up + (uint32_t)((mt*16 + (lane & 15)) * 144
                                             + ((lane >> 4) * 8 + k2 * 16) * 2);
            ldsm_x4(a4[0], a4[1], a4[2], a4[3], aaddr);
            uint32_t b4[4];
            int rowB = nh2*16 + (lane & 7) + (((lane >> 4) & 1) << 3);
            uint32_t baddr = uv + (uint32_t)(rowB * 144
                                             + (((lane >> 3) & 1) * 8 + k2 * 16) * 2);
            ldsm_x4(b4[0], b4[1], b4[2], b4[3], baddr);
            mma_f16(c[0], a4, b4[0], b4[1]);
            mma_f16(c[1], a4, b4[2], b4[3]);
        }
        #pragma unroll
        for (int j = 0; j < 2; j++)
            #pragma unroll
            for (int hf = 0; hf < 2; hf++) {
                int t = mt*16 + (lane >> 2) + hf*8;
                if (t < 49) {
                    int d0 = nh2*16 + j*8 + (lane & 3)*2;
                    size_t o = (size_t)(bn * T + t) * CDIM + head * DH + d0;
                    *(__half2*)(g_att16 + o) = __floats2half2_rn(c[j][hf*2+0], c[j][hf*2+1]);
                }
            }
    }
}

// ---------------------------------------------------------------------------
extern "C" void kernel_launch(void* const* d_in, const int* in_sizes, int n_in,
                              void* d_out, int out_size)
{
    const float* x     = (const float*)d_in[0];
    const float* wqkv  = (const float*)d_in[1];
    const float* bqkv  = (const float*)d_in[2];
    const float* wproj = (const float*)d_in[3];
    const float* bproj = (const float*)d_in[4];
    const float* table = (const float*)d_in[5];
    float* out = (float*)d_out;

    cudaFuncSetAttribute(gemm_mma<0>, cudaFuncAttributeMaxDynamicSharedMemorySize, SMEM_DYN);
    cudaFuncSetAttribute(gemm_mma<1>, cudaFuncAttributeMaxDynamicSharedMemorySize, SMEM_DYN);

    __half *wq16, *wp16;
    cudaGetSymbolAddress((void**)&wq16, g_wq16);
    cudaGetSymbolAddress((void**)&wp16, g_wp16);

    gather_convert_x<<<(MROWS * (CDIM/4) + 255) / 256, 256>>>(x);
    convert_w<<<(NQKV * CDIM / 4 + 255) / 256, 256>>>(wqkv,  wq16, NQKV * CDIM / 4);
    convert_w<<<(CDIM * CDIM / 4 + 255) / 256, 256>>>(wproj, wp16, CDIM * CDIM / 4);

    dim3 g1(NQKV / 128, MROWS / 128);     // (9, 784)
    gemm_mma<0><<<g1, 256, SMEM_DYN>>>(bqkv, nullptr);

    attn_kernel<<<BN * NH, 256>>>(table);

    dim3 g2(CDIM / 128, MROWS / 128);     // (3, 784)
    gemm_mma<1><<<g2, 256, SMEM_DYN>>>(bproj, out);
}

// round 15
// speedup vs baseline: 1.3126x; 1.3126x over previous
#include <cuda_runtime.h>
#include <cuda_fp16.h>
#include <cstdint>

// ---------------- Problem constants ----------------
#define BATCH   32
#define HW      56
#define CDIM    384
#define NH      12
#define DH      32
#define WS      7
#define T       49
#define NWIN    64
#define BN      (BATCH*NWIN)       // 2048
#define MROWS   (BN*T)             // 100352
#define NQKV    (3*CDIM)           // 1152
#define SCALE   0.17677669529663687f

// ---------------- Scratch (static device memory) ----------------
__device__ __half  g_qkv16[(size_t)BN * NH * 3 * T * DH];  // attn input, fp16
__device__ __half  g_x16[(size_t)MROWS * CDIM];            // gathered x, fp16
__device__ __half  g_att16[(size_t)MROWS * CDIM];          // attention out, fp16
__device__ __half  g_wq16[(size_t)NQKV * CDIM];            // qkv weights, fp16
__device__ __half  g_wp16[(size_t)CDIM * CDIM];            // proj weights, fp16

// ---------------- helpers ----------------
__device__ __forceinline__ uint32_t smem_u32(const void* p) {
    uint32_t a;
    asm("{ .reg .u64 t; cvta.to.shared.u64 t, %1; cvt.u32.u64 %0, t; }" : "=r"(a) : "l"(p));
    return a;
}

__device__ __forceinline__ void ldsm_x4(uint32_t& r0, uint32_t& r1, uint32_t& r2, uint32_t& r3,
                                        uint32_t addr) {
    asm volatile("ldmatrix.sync.aligned.m8n8.x4.shared.b16 {%0,%1,%2,%3}, [%4];"
                 : "=r"(r0), "=r"(r1), "=r"(r2), "=r"(r3) : "r"(addr));
}

__device__ __forceinline__ void mma_f16(float* c, const uint32_t* a, uint32_t b0, uint32_t b1) {
    asm volatile(
        "mma.sync.aligned.m16n8k16.row.col.f32.f16.f16.f32 "
        "{%0,%1,%2,%3}, {%4,%5,%6,%7}, {%8,%9}, {%0,%1,%2,%3};"
        : "+f"(c[0]), "+f"(c[1]), "+f"(c[2]), "+f"(c[3])
        : "r"(a[0]), "r"(a[1]), "r"(a[2]), "r"(a[3]), "r"(b0), "r"(b1));
}

__device__ __forceinline__ void cp16(uint32_t dst, const void* src) {
    asm volatile("cp.async.cg.shared.global [%0], [%1], 16;" :: "r"(dst), "l"(src));
}

// ---------------------------------------------------------------------------
// Precompute 1: gather x (roll -3, window partition) -> fp16 [MROWS,384]
// ---------------------------------------------------------------------------
__global__ __launch_bounds__(256)
void gather_convert_x(const float* __restrict__ x)
{
    int idx = blockIdx.x * 256 + threadIdx.x;
    if (idx >= MROWS * (CDIM / 4)) return;
    int row = idx / (CDIM / 4);
    int c4  = idx % (CDIM / 4);
    int bn = row / T, t = row % T;
    int b = bn >> 6, win = bn & 63;
    int wr = win >> 3, wc = win & 7;
    int tr = t / WS, tc = t % WS;
    int h = wr * WS + tr + 3; if (h >= HW) h -= HW;
    int w = wc * WS + tc + 3; if (w >= HW) w -= HW;
    float4 v = *(const float4*)(x + ((size_t)((b * HW + h) * HW + w)) * CDIM + c4 * 4);
    size_t o = (size_t)row * CDIM + c4 * 4;
    *(__half2*)(g_x16 + o)     = __floats2half2_rn(v.x, v.y);
    *(__half2*)(g_x16 + o + 2) = __floats2half2_rn(v.z, v.w);
}

// ---------------------------------------------------------------------------
// Precompute 2: fp32 -> fp16 (weights)
// ---------------------------------------------------------------------------
__global__ __launch_bounds__(256)
void convert_w(const float* __restrict__ src, __half* __restrict__ dst, int n4)
{
    int idx = blockIdx.x * 256 + threadIdx.x;
    if (idx >= n4) return;
    float4 v = *(const float4*)(src + (size_t)idx * 4);
    size_t o = (size_t)idx * 4;
    *(__half2*)(dst + o)     = __floats2half2_rn(v.x, v.y);
    *(__half2*)(dst + o + 2) = __floats2half2_rn(v.z, v.w);
}

// ---------------------------------------------------------------------------
// mma.sync GEMM, BK=32, 3-stage cp.async pipeline, ONE __syncthreads per chunk,
// fragment double-buffering over ks (LDSM hidden behind MMAs).
// C[128,128] = A[128,384] @ B[128,384]^T  (plain fp16)
// Swizzled smem: rows of 64B, 16B line l at (l ^ ((row>>1)&3)).
// ---------------------------------------------------------------------------
#define TEN_BYTES  (128 * 64)           // 8192 B per tensor
#define STG_BYTES  (2 * TEN_BYTES)      // 16384 B per stage (A, B)
#define NSTAGE     3
#define SMEM_DYN   (NSTAGE * STG_BYTES) // 49152 B
#define NKIT       (CDIM / 32)          // 12

__device__ __forceinline__ uint32_t swz_off(int row, int line) {
    return (uint32_t)(row * 64 + ((line ^ ((row >> 1) & 3)) << 4));
}

template<int MODE>
__global__ __launch_bounds__(256, 2)
void gemm_mma(const float* __restrict__ bias, float* __restrict__ out)
{
    extern __shared__ __align__(16) char dynsmem[];
    const uint32_t u0 = smem_u32(dynsmem);

    const __half* __restrict__ aP = (MODE == 0) ? g_x16  : g_att16;
    const __half* __restrict__ bP = (MODE == 0) ? g_wq16 : g_wp16;

    const int tid  = threadIdx.x;
    const int lane = tid & 31;
    const int wid  = tid >> 5;
    const int wm   = wid & 1;
    const int wn   = wid >> 1;
    const int mbase = blockIdx.y * 128;
    const int nbase = blockIdx.x * 128;

    float acc[4][4][4];
    #pragma unroll
    for (int i = 0; i < 4; i++)
        #pragma unroll
        for (int j = 0; j < 4; j++)
            #pragma unroll
            for (int k = 0; k < 4; k++) acc[i][j][k] = 0.f;

    const int r0g = tid >> 2, q0g = tid & 3;
    const int r1g = r0g + 64;
    const uint32_t s0 = swz_off(r0g, q0g);
    const uint32_t s1 = swz_off(r1g, q0g);

    auto issue = [&](int st, int k0) {
        uint32_t base = u0 + st * STG_BYTES;
        size_t a0 = (size_t)(mbase + r0g) * CDIM + k0 + q0g * 8;
        size_t a1 = a0 + (size_t)64 * CDIM;
        size_t b0 = (size_t)(nbase + r0g) * CDIM + k0 + q0g * 8;
        size_t b1 = b0 + (size_t)64 * CDIM;
        cp16(base + s0,             aP + a0);
        cp16(base + s1,             aP + a1);
        cp16(base + TEN_BYTES + s0, bP + b0);
        cp16(base + TEN_BYTES + s1, bP + b1);
        asm volatile("cp.async.commit_group;");
    };

    const int rA  = wm * 64 + (lane & 15);
    const int cA0 = lane >> 4;
    const int sxA = (rA >> 1) & 3;
    const int rB  = wn * 32 + (lane & 7) + (((lane >> 4) & 1) << 3);
    const int cB0 = (lane >> 3) & 1;
    const int sxB = (rB >> 1) & 3;
    const uint32_t aBase = (uint32_t)(rA * 64);
    const uint32_t bBase = (uint32_t)(rB * 64);

    issue(0, 0);
    issue(1, 32);

    uint32_t ah[2][4][4], bh[2][8];

    int stage = 0;
    for (int it = 0; it < NKIT; it++) {
        asm volatile("cp.async.wait_group 1;");
        __syncthreads();

        if (it + 2 < NKIT) {
            int st2 = stage + 2; if (st2 >= NSTAGE) st2 -= NSTAGE;
            issue(st2, (it + 2) * 32);
        }

        const uint32_t uA = u0 + stage * STG_BYTES;
        const uint32_t uB = uA + TEN_BYTES;

        // Load ks=0 fragments into buffer 0
        {
            const uint32_t aOff = aBase + (uint32_t)((cA0 ^ sxA) << 4);
            const uint32_t bOff = bBase + (uint32_t)((cB0 ^ sxB) << 4);
            #pragma unroll
            for (int mt = 0; mt < 4; mt++) {
                uint32_t off = aOff + (uint32_t)(mt * 1024);
                ldsm_x4(ah[0][mt][0], ah[0][mt][1], ah[0][mt][2], ah[0][mt][3], uA + off);
            }
            #pragma unroll
            for (int nt2 = 0; nt2 < 2; nt2++) {
                uint32_t off = bOff + (uint32_t)(nt2 * 1024);
                ldsm_x4(bh[0][nt2*4+0], bh[0][nt2*4+1], bh[0][nt2*4+2], bh[0][nt2*4+3], uB + off);
            }
        }

        #pragma unroll
        for (int ks = 0; ks < 2; ks++) {
            const int cur = ks & 1, nxt = cur ^ 1;
            if (ks + 1 < 2) {
                // Prefetch next ks fragments before issuing this ks's MMAs
                const uint32_t aOff = aBase + (uint32_t)(((2*(ks+1) + cA0) ^ sxA) << 4);
                const uint32_t bOff = bBase + (uint32_t)(((2*(ks+1) + cB0) ^ sxB) << 4);
                #pragma unroll
                for (int mt = 0; mt < 4; mt++) {
                    uint32_t off = aOff + (uint32_t)(mt * 1024);
                    ldsm_x4(ah[nxt][mt][0], ah[nxt][mt][1], ah[nxt][mt][2], ah[nxt][mt][3], uA + off);
                }
                #pragma unroll
                for (int nt2 = 0; nt2 < 2; nt2++) {
                    uint32_t off = bOff + (uint32_t)(nt2 * 1024);
                    ldsm_x4(bh[nxt][nt2*4+0], bh[nxt][nt2*4+1], bh[nxt][nt2*4+2], bh[nxt][nt2*4+3], uB + off);
                }
            }
            #pragma unroll
            for (int mt = 0; mt < 4; mt++)
                #pragma unroll
                for (int nt = 0; nt < 4; nt++)
                    mma_f16(acc[mt][nt], ah[cur][mt], bh[cur][nt*2+0], bh[cur][nt*2+1]);
        }
        stage++; if (stage >= NSTAGE) stage -= NSTAGE;
    }

    // ---- Epilogue ----
    #pragma unroll
    for (int mt = 0; mt < 4; mt++) {
        #pragma unroll
        for (int hf = 0; hf < 2; hf++) {
            int m = mbase + wm * 64 + mt * 16 + (lane >> 2) + hf * 8;
            int bn = m / T, t = m % T;
            if (MODE == 0) {
                #pragma unroll
                for (int nt = 0; nt < 4; nt++) {
                    int col = nbase + wn * 32 + nt * 8 + (lane & 3) * 2;
                    int which = col / CDIM;
                    int rem   = col - which * CDIM;
                    int head  = rem >> 5;
                    int d     = rem & 31;
                    float vx = acc[mt][nt][hf*2+0] + __ldg(&bias[col]);
                    float vy = acc[mt][nt][hf*2+1] + __ldg(&bias[col+1]);
                    *(__half2*)(g_qkv16 + ((size_t)(bn * NH + head) * 3 + which) * (T * DH)
                                + t * DH + d) = __floats2half2_rn(vx, vy);
                }
            } else {
                int b = bn >> 6, win = bn & 63;
                int wr = win >> 3, wc = win & 7;
                int tr = t / WS, tc = t % WS;
                int h = wr * WS + tr + 3; if (h >= HW) h -= HW;
                int w = wc * WS + tc + 3; if (w >= HW) w -= HW;
                float* orow = out + ((size_t)((b * HW + h) * HW + w)) * CDIM;
                #pragma unroll
                for (int nt = 0; nt < 4; nt++) {
                    int col = nbase + wn * 32 + nt * 8 + (lane & 3) * 2;
                    float2 v;
                    v.x = acc[mt][nt][hf*2+0] + __ldg(&bias[col]);
                    v.y = acc[mt][nt][hf*2+1] + __ldg(&bias[col+1]);
                    *(float2*)(orow + col) = v;
                }
            }
        }
    }
}

// ---------------------------------------------------------------------------
// Attention: tensor-core QK^T and PV, softmax fused into QK epilogue.
// QK epilogue writes exp(val) (unnormalized) to Pp and accumulates row sums;
// PV scales its output row by 1/rowsum. No separate softmax phase, no S buffer.
// ---------------------------------------------------------------------------
__global__ __launch_bounds__(256)
void attn_kernel(const float* __restrict__ table)
{
    const int bnh  = blockIdx.x;
    const int bn   = bnh / NH;
    const int head = bnh % NH;
    const int tid  = threadIdx.x;
    const int lane = tid & 31;
    const int wid  = tid >> 5;

    __shared__ __align__(16) __half qs[64 * 40];   // [t][40], 80B stride
    __shared__ __align__(16) __half ks[64 * 40];   // [s][40]
    __shared__ __align__(16) __half vT[32 * 72];   // [d][72], 144B stride
    __shared__ __align__(16) __half Pp[64 * 72];   // [t][72], fp16 unnormalized P
    __shared__ float rsum[2][64];                  // per-ng partial row sums
    __shared__ int rid[49];

    // Zero vT (pad cols s>=49 must be finite zeros for PV)
    {
        uint4 z = make_uint4(0,0,0,0);
        uint4* vz = (uint4*)vT;                 // 32*72/8 = 288
        for (int i = tid; i < 288; i += 256) vz[i] = z;
    }
    __syncthreads();

    const __half* base = g_qkv16 + (size_t)(bn * NH + head) * (3 * T * DH);
    {
        const uint4* bq = (const uint4*)base;
        for (int i = tid; i < 392; i += 256) {
            int sec = (i >= 196);
            int rem = i - sec * 196;
            int t = rem >> 2, ch = rem & 3;
            uint4 v = bq[i];
            *(uint4*)((sec ? ks : qs) + t * 40 + ch * 8) = v;
        }
    }
    {
        const __half2* bv = (const __half2*)(base + 2 * T * DH);
        for (int i = tid; i < 784; i += 256) {
            int t = i >> 4, d2 = i & 15;
            __half2 v = bv[i];
            vT[(d2 * 2)     * 72 + t] = __low2half(v);
            vT[(d2 * 2 + 1) * 72 + t] = __high2half(v);
        }
    }
    if (tid < 49) {
        int win = bn & 63;
        int wr = win >> 3, wc = win & 7;
        int tr = (tid * 37) >> 8, tc = tid - tr * 7;
        int h = wr * WS + tr, w = wc * WS + tc;
        int rh = (h < 49) ? 0 : ((h < 53) ? 1 : 2);
        int rw = (w < 49) ? 0 : ((w < 53) ? 1 : 2);
        rid[tid] = rh * 3 + rw;
    }
    __syncthreads();

    // ---- QK^T + fused exp/row-sum: warp (mt = wid>>1, ng = wid&1) ----
    {
        const int mt = wid >> 1, ng = wid & 1;
        const uint32_t uq = smem_u32(qs), uk = smem_u32(ks);
        uint32_t a[2][4];
        #pragma unroll
        for (int k2 = 0; k2 < 2; k2++) {
            uint32_t addr = uq + (uint32_t)((mt*16 + (lane & 15)) * 80
                                            + ((lane >> 4) * 8 + k2 * 16) * 2);
            ldsm_x4(a[k2][0], a[k2][1], a[k2][2], a[k2][3], addr);
        }
        uint32_t b[2][8];
        #pragma unroll
        for (int k2 = 0; k2 < 2; k2++)
            #pragma unroll
            for (int nt2 = 0; nt2 < 2; nt2++) {
                int rowB = ng*32 + nt2*16 + (lane & 7) + (((lane >> 4) & 1) << 3);
                uint32_t addr = uk + (uint32_t)(rowB * 80
                                                + (((lane >> 3) & 1) * 8 + k2 * 16) * 2);
                ldsm_x4(b[k2][nt2*4+0], b[k2][nt2*4+1], b[k2][nt2*4+2], b[k2][nt2*4+3], addr);
            }
        float c[4][4];
        #pragma unroll
        for (int j = 0; j < 4; j++)
            #pragma unroll
            for (int e = 0; e < 4; e++) c[j][e] = 0.f;
        #pragma unroll
        for (int j = 0; j < 4; j++) {
            mma_f16(c[j], a[0], b[0][j*2+0], b[0][j*2+1]);
            mma_f16(c[j], a[1], b[1][j*2+0], b[1][j*2+1]);
        }
        // fragment -> exp -> Pp (full 64x64 coverage incl. zero padding) + row sums
        #pragma unroll
        for (int hf = 0; hf < 2; hf++) {
            int t = mt*16 + (lane >> 2) + hf*8;
            bool tv = (t < 49);
            int tr = 0, tc = 0, rt = 0;
            if (tv) { tr = (t * 37) >> 8; tc = t - tr * 7; rt = rid[t]; }
            float rs = 0.f;
            #pragma unroll
            for (int j = 0; j < 4; j++) {
                float ev[2];
                #pragma unroll
                for (int e = 0; e < 2; e++) {
                    int s = ng*32 + j*8 + (lane & 3)*2 + e;
                    float v = 0.f;
                    if (tv && s < 49) {
                        int sr = (s * 37) >> 8, sc = s - sr * 7;
                        float val = c[j][hf*2+e] * SCALE
                            + __ldg(&table[((tr - sr + 6)*13 + (tc - sc + 6)) * NH + head]);
                        if (rt != rid[s]) val -= 100.0f;
                        v = __expf(val);
                    }
                    ev[e] = v;
                    rs += v;
                }
                int s0i = ng*32 + j*8 + (lane & 3)*2;
                *(__half2*)(Pp + t*72 + s0i) = __floats2half2_rn(ev[0], ev[1]);
            }
            // reduce rs across the 4 lanes sharing this row
            rs += __shfl_xor_sync(0xFFFFFFFFu, rs, 1);
            rs += __shfl_xor_sync(0xFFFFFFFFu, rs, 2);
            if ((lane & 3) == 0) rsum[ng][t] = rs;
        }
    }
    __syncthreads();

    // ---- PV: warp (mt = wid>>1, nh2 = wid&1); out tile 16x16 per warp ----
    {
        const int mt = wid >> 1, nh2 = wid & 1;
        const uint32_t up = smem_u32(Pp), uv = smem_u32(vT);
        float c[2][4];
        #pragma unroll
        for (int j = 0; j < 2; j++)
            #pragma unroll
            for (int e = 0; e < 4; e++) c[j][e] = 0.f;
        #pragma unroll
        for (int k2 = 0; k2 < 4; k2++) {
            uint32_t a4[4];
            uint32_t aaddr = up + (uint32_t)((mt*16 + (lane & 15)) * 144
                                             + ((lane >> 4) * 8 + k2 * 16) * 2);
            ldsm_x4(a4[0], a4[1], a4[2], a4[3], aaddr);
            uint32_t b4[4];
            int rowB = nh2*16 + (lane & 7) + (((lane >> 4) & 1) << 3);
            uint32_t baddr = uv + (uint32_t)(rowB * 144
                                             + (((lane >> 3) & 1) * 8 + k2 * 16) * 2);
            ldsm_x4(b4[0], b4[1], b4[2], b4[3], baddr);
            mma_f16(c[0], a4, b4[0], b4[1]);
            mma_f16(c[1], a4, b4[2], b4[3]);
        }
        #pragma unroll
        for (int j = 0; j < 2; j++)
            #pragma unroll
            for (int hf = 0; hf < 2; hf++) {
                int t = mt*16 + (lane >> 2) + hf*8;
                if (t < 49) {
                    float inv = __frcp_rn(rsum[0][t] + rsum[1][t]);
                    int d0 = nh2*16 + j*8 + (lane & 3)*2;
                    size_t o = (size_t)(bn * T + t) * CDIM + head * DH + d0;
                    *(__half2*)(g_att16 + o) =
                        __floats2half2_rn(c[j][hf*2+0] * inv, c[j][hf*2+1] * inv);
                }
            }
    }
}

// ---------------------------------------------------------------------------
extern "C" void kernel_launch(void* const* d_in, const int* in_sizes, int n_in,
                              void* d_out, int out_size)
{
    const float* x     = (const float*)d_in[0];
    const float* wqkv  = (const float*)d_in[1];
    const float* bqkv  = (const float*)d_in[2];
    const float* wproj = (const float*)d_in[3];
    const float* bproj = (const float*)d_in[4];
    const float* table = (const float*)d_in[5];
    float* out = (float*)d_out;

    cudaFuncSetAttribute(gemm_mma<0>, cudaFuncAttributeMaxDynamicSharedMemorySize, SMEM_DYN);
    cudaFuncSetAttribute(gemm_mma<1>, cudaFuncAttributeMaxDynamicSharedMemorySize, SMEM_DYN);

    __half *wq16, *wp16;
    cudaGetSymbolAddress((void**)&wq16, g_wq16);
    cudaGetSymbolAddress((void**)&wp16, g_wp16);

    gather_convert_x<<<(MROWS * (CDIM/4) + 255) / 256, 256>>>(x);
    convert_w<<<(NQKV * CDIM / 4 + 255) / 256, 256>>>(wqkv,  wq16, NQKV * CDIM / 4);
    convert_w<<<(CDIM * CDIM / 4 + 255) / 256, 256>>>(wproj, wp16, CDIM * CDIM / 4);

    dim3 g1(NQKV / 128, MROWS / 128);     // (9, 784)
    gemm_mma<0><<<g1, 256, SMEM_DYN>>>(bqkv, nullptr);

    attn_kernel<<<BN * NH, 256>>>(table);

    dim3 g2(CDIM / 128, MROWS / 128);     // (3, 784)
    gemm_mma<1><<<g2, 256, SMEM_DYN>>>(bproj, out);
}

// round 17
// speedup vs baseline: 1.3173x; 1.0036x over previous
#include <cuda_runtime.h>
#include <cuda_fp16.h>
#include <cstdint>

// ---------------- Problem constants ----------------
#define BATCH   32
#define HW      56
#define CDIM    384
#define NH      12
#define DH      32
#define WS      7
#define T       49
#define NWIN    64
#define BN      (BATCH*NWIN)       // 2048
#define MROWS   (BN*T)             // 100352
#define NQKV    (3*CDIM)           // 1152
#define SCALE   0.17677669529663687f

// ---------------- Scratch (static device memory) ----------------
__device__ __half  g_qkv16[(size_t)BN * NH * 3 * T * DH];  // attn input, fp16
__device__ __half  g_x16[(size_t)MROWS * CDIM];            // gathered x, fp16
__device__ __half  g_att16[(size_t)MROWS * CDIM];          // attention out, fp16
__device__ __half  g_wq16[(size_t)NQKV * CDIM];            // qkv weights, fp16
__device__ __half  g_wp16[(size_t)CDIM * CDIM];            // proj weights, fp16

// ---------------- helpers ----------------
__device__ __forceinline__ uint32_t smem_u32(const void* p) {
    uint32_t a;
    asm("{ .reg .u64 t; cvta.to.shared.u64 t, %1; cvt.u32.u64 %0, t; }" : "=r"(a) : "l"(p));
    return a;
}

__device__ __forceinline__ void ldsm_x4(uint32_t& r0, uint32_t& r1, uint32_t& r2, uint32_t& r3,
                                        uint32_t addr) {
    asm volatile("ldmatrix.sync.aligned.m8n8.x4.shared.b16 {%0,%1,%2,%3}, [%4];"
                 : "=r"(r0), "=r"(r1), "=r"(r2), "=r"(r3) : "r"(addr));
}

__device__ __forceinline__ void mma_f16(float* c, const uint32_t* a, uint32_t b0, uint32_t b1) {
    asm volatile(
        "mma.sync.aligned.m16n8k16.row.col.f32.f16.f16.f32 "
        "{%0,%1,%2,%3}, {%4,%5,%6,%7}, {%8,%9}, {%0,%1,%2,%3};"
        : "+f"(c[0]), "+f"(c[1]), "+f"(c[2]), "+f"(c[3])
        : "r"(a[0]), "r"(a[1]), "r"(a[2]), "r"(a[3]), "r"(b0), "r"(b1));
}

__device__ __forceinline__ void cp16(uint32_t dst, const void* src) {
    asm volatile("cp.async.cg.shared.global [%0], [%1], 16;" :: "r"(dst), "l"(src));
}

// ---------------------------------------------------------------------------
// Precompute 1: gather x (roll -3, window partition) -> fp16 [MROWS,384]
// ---------------------------------------------------------------------------
__global__ __launch_bounds__(256)
void gather_convert_x(const float* __restrict__ x)
{
    int idx = blockIdx.x * 256 + threadIdx.x;
    if (idx >= MROWS * (CDIM / 4)) return;
    int row = idx / (CDIM / 4);
    int c4  = idx % (CDIM / 4);
    int bn = row / T, t = row % T;
    int b = bn >> 6, win = bn & 63;
    int wr = win >> 3, wc = win & 7;
    int tr = t / WS, tc = t % WS;
    int h = wr * WS + tr + 3; if (h >= HW) h -= HW;
    int w = wc * WS + tc + 3; if (w >= HW) w -= HW;
    float4 v = *(const float4*)(x + ((size_t)((b * HW + h) * HW + w)) * CDIM + c4 * 4);
    size_t o = (size_t)row * CDIM + c4 * 4;
    *(__half2*)(g_x16 + o)     = __floats2half2_rn(v.x, v.y);
    *(__half2*)(g_x16 + o + 2) = __floats2half2_rn(v.z, v.w);
}

// ---------------------------------------------------------------------------
// Precompute 2: fp32 -> fp16 (weights)
// ---------------------------------------------------------------------------
__global__ __launch_bounds__(256)
void convert_w(const float* __restrict__ src, __half* __restrict__ dst, int n4)
{
    int idx = blockIdx.x * 256 + threadIdx.x;
    if (idx >= n4) return;
    float4 v = *(const float4*)(src + (size_t)idx * 4);
    size_t o = (size_t)idx * 4;
    *(__half2*)(dst + o)     = __floats2half2_rn(v.x, v.y);
    *(__half2*)(dst + o + 2) = __floats2half2_rn(v.z, v.w);
}

// ---------------------------------------------------------------------------
// mma.sync GEMM, BK=32, 4-stage cp.async pipeline (prefetch distance 3).
// Steady state: wait_group 2.  Tail: wait_group 1 / 0 so chunk `it` is
// PROVABLY complete at every iteration (fixes the tail race).
// ONE __syncthreads per chunk; fragment double-buffering over ks.
// C[128,128] = A[128,384] @ B[128,384]^T  (plain fp16)
// Swizzled smem: rows of 64B, 16B line l at (l ^ ((row>>1)&3)).
// ---------------------------------------------------------------------------
#define TEN_BYTES  (128 * 64)           // 8192 B per tensor
#define STG_BYTES  (2 * TEN_BYTES)      // 16384 B per stage (A, B)
#define NSTAGE     4
#define SMEM_DYN   (NSTAGE * STG_BYTES) // 65536 B
#define NKIT       (CDIM / 32)          // 12

__device__ __forceinline__ uint32_t swz_off(int row, int line) {
    return (uint32_t)(row * 64 + ((line ^ ((row >> 1) & 3)) << 4));
}

template<int MODE>
__global__ __launch_bounds__(256, 2)
void gemm_mma(const float* __restrict__ bias, float* __restrict__ out)
{
    extern __shared__ __align__(16) char dynsmem[];
    const uint32_t u0 = smem_u32(dynsmem);

    const __half* __restrict__ aP = (MODE == 0) ? g_x16  : g_att16;
    const __half* __restrict__ bP = (MODE == 0) ? g_wq16 : g_wp16;

    const int tid  = threadIdx.x;
    const int lane = tid & 31;
    const int wid  = tid >> 5;
    const int wm   = wid & 1;
    const int wn   = wid >> 1;
    const int mbase = blockIdx.y * 128;
    const int nbase = blockIdx.x * 128;

    float acc[4][4][4];
    #pragma unroll
    for (int i = 0; i < 4; i++)
        #pragma unroll
        for (int j = 0; j < 4; j++)
            #pragma unroll
            for (int k = 0; k < 4; k++) acc[i][j][k] = 0.f;

    const int r0g = tid >> 2, q0g = tid & 3;
    const int r1g = r0g + 64;
    const uint32_t s0 = swz_off(r0g, q0g);
    const uint32_t s1 = swz_off(r1g, q0g);

    auto issue = [&](int st, int k0) {
        uint32_t base = u0 + st * STG_BYTES;
        size_t a0 = (size_t)(mbase + r0g) * CDIM + k0 + q0g * 8;
        size_t a1 = a0 + (size_t)64 * CDIM;
        size_t b0 = (size_t)(nbase + r0g) * CDIM + k0 + q0g * 8;
        size_t b1 = b0 + (size_t)64 * CDIM;
        cp16(base + s0,             aP + a0);
        cp16(base + s1,             aP + a1);
        cp16(base + TEN_BYTES + s0, bP + b0);
        cp16(base + TEN_BYTES + s1, bP + b1);
        asm volatile("cp.async.commit_group;");
    };

    const int rA  = wm * 64 + (lane & 15);
    const int cA0 = lane >> 4;
    const int sxA = (rA >> 1) & 3;
    const int rB  = wn * 32 + (lane & 7) + (((lane >> 4) & 1) << 3);
    const int cB0 = (lane >> 3) & 1;
    const int sxB = (rB >> 1) & 3;
    const uint32_t aBase = (uint32_t)(rA * 64);
    const uint32_t bBase = (uint32_t)(rB * 64);

    // Prologue: distance-3 prefetch
    issue(0, 0);
    issue(1, 32);
    issue(2, 64);

    uint32_t ah[2][4][4], bh[2][8];

    int stage = 0;
    for (int it = 0; it < NKIT; it++) {
        // Completion guarantee for chunk `it`:
        //  - while issuing continues, 3 groups pending -> wait_group 2
        //  - tail: pending count shrinks; tighten the bound accordingly.
        if (it < NKIT - 2)       asm volatile("cp.async.wait_group 2;");
        else if (it == NKIT - 2) asm volatile("cp.async.wait_group 1;");
        else                     asm volatile("cp.async.wait_group 0;");
        __syncthreads();

        if (it + 3 < NKIT) {
            int st3 = stage + 3; if (st3 >= NSTAGE) st3 -= NSTAGE;
            issue(st3, (it + 3) * 32);
        }

        const uint32_t uA = u0 + stage * STG_BYTES;
        const uint32_t uB = uA + TEN_BYTES;

        // Load ks=0 fragments into buffer 0
        {
            const uint32_t aOff = aBase + (uint32_t)((cA0 ^ sxA) << 4);
            const uint32_t bOff = bBase + (uint32_t)((cB0 ^ sxB) << 4);
            #pragma unroll
            for (int mt = 0; mt < 4; mt++) {
                uint32_t off = aOff + (uint32_t)(mt * 1024);
                ldsm_x4(ah[0][mt][0], ah[0][mt][1], ah[0][mt][2], ah[0][mt][3], uA + off);
            }
            #pragma unroll
            for (int nt2 = 0; nt2 < 2; nt2++) {
                uint32_t off = bOff + (uint32_t)(nt2 * 1024);
                ldsm_x4(bh[0][nt2*4+0], bh[0][nt2*4+1], bh[0][nt2*4+2], bh[0][nt2*4+3], uB + off);
            }
        }

        #pragma unroll
        for (int ks = 0; ks < 2; ks++) {
            const int cur = ks & 1, nxt = cur ^ 1;
            if (ks + 1 < 2) {
                const uint32_t aOff = aBase + (uint32_t)(((2*(ks+1) + cA0) ^ sxA) << 4);
                const uint32_t bOff = bBase + (uint32_t)(((2*(ks+1) + cB0) ^ sxB) << 4);
                #pragma unroll
                for (int mt = 0; mt < 4; mt++) {
                    uint32_t off = aOff + (uint32_t)(mt * 1024);
                    ldsm_x4(ah[nxt][mt][0], ah[nxt][mt][1], ah[nxt][mt][2], ah[nxt][mt][3], uA + off);
                }
                #pragma unroll
                for (int nt2 = 0; nt2 < 2; nt2++) {
                    uint32_t off = bOff + (uint32_t)(nt2 * 1024);
                    ldsm_x4(bh[nxt][nt2*4+0], bh[nxt][nt2*4+1], bh[nxt][nt2*4+2], bh[nxt][nt2*4+3], uB + off);
                }
            }
            #pragma unroll
            for (int mt = 0; mt < 4; mt++)
                #pragma unroll
                for (int nt = 0; nt < 4; nt++)
                    mma_f16(acc[mt][nt], ah[cur][mt], bh[cur][nt*2+0], bh[cur][nt*2+1]);
        }
        stage++; if (stage >= NSTAGE) stage -= NSTAGE;
    }

    // ---- Epilogue ----
    #pragma unroll
    for (int mt = 0; mt < 4; mt++) {
        #pragma unroll
        for (int hf = 0; hf < 2; hf++) {
            int m = mbase + wm * 64 + mt * 16 + (lane >> 2) + hf * 8;
            int bn = m / T, t = m % T;
            if (MODE == 0) {
                #pragma unroll
                for (int nt = 0; nt < 4; nt++) {
                    int col = nbase + wn * 32 + nt * 8 + (lane & 3) * 2;
                    int which = col / CDIM;
                    int rem   = col - which * CDIM;
                    int head  = rem >> 5;
                    int d     = rem & 31;
                    float vx = acc[mt][nt][hf*2+0] + __ldg(&bias[col]);
                    float vy = acc[mt][nt][hf*2+1] + __ldg(&bias[col+1]);
                    *(__half2*)(g_qkv16 + ((size_t)(bn * NH + head) * 3 + which) * (T * DH)
                                + t * DH + d) = __floats2half2_rn(vx, vy);
                }
            } else {
                int b = bn >> 6, win = bn & 63;
                int wr = win >> 3, wc = win & 7;
                int tr = t / WS, tc = t % WS;
                int h = wr * WS + tr + 3; if (h >= HW) h -= HW;
                int w = wc * WS + tc + 3; if (w >= HW) w -= HW;
                float* orow = out + ((size_t)((b * HW + h) * HW + w)) * CDIM;
                #pragma unroll
                for (int nt = 0; nt < 4; nt++) {
                    int col = nbase + wn * 32 + nt * 8 + (lane & 3) * 2;
                    float2 v;
                    v.x = acc[mt][nt][hf*2+0] + __ldg(&bias[col]);
                    v.y = acc[mt][nt][hf*2+1] + __ldg(&bias[col+1]);
                    *(float2*)(orow + col) = v;
                }
            }
        }
    }
}

// ---------------------------------------------------------------------------
// Attention: tensor-core QK^T and PV, softmax fused into QK epilogue.
// QK epilogue writes exp(val) (unnormalized) to Pp and accumulates row sums;
// PV scales its output row by 1/rowsum. No separate softmax phase, no S buffer.
// ---------------------------------------------------------------------------
__global__ __launch_bounds__(256)
void attn_kernel(const float* __restrict__ table)
{
    const int bnh  = blockIdx.x;
    const int bn   = bnh / NH;
    const int head = bnh % NH;
    const int tid  = threadIdx.x;
    const int lane = tid & 31;
    const int wid  = tid >> 5;

    __shared__ __align__(16) __half qs[64 * 40];   // [t][40], 80B stride
    __shared__ __align__(16) __half ks[64 * 40];   // [s][40]
    __shared__ __align__(16) __half vT[32 * 72];   // [d][72], 144B stride
    __shared__ __align__(16) __half Pp[64 * 72];   // [t][72], fp16 unnormalized P
    __shared__ float rsum[2][64];                  // per-ng partial row sums
    __shared__ int rid[49];

    // Zero vT (pad cols s>=49 must be finite zeros for PV)
    {
        uint4 z = make_uint4(0,0,0,0);
        uint4* vz = (uint4*)vT;                 // 32*72/8 = 288
        for (int i = tid; i < 288; i += 256) vz[i] = z;
    }
    __syncthreads();

    const __half* base = g_qkv16 + (size_t)(bn * NH + head) * (3 * T * DH);
    {
        const uint4* bq = (const uint4*)base;
        for (int i = tid; i < 392; i += 256) {
            int sec = (i >= 196);
            int rem = i - sec * 196;
            int t = rem >> 2, ch = rem & 3;
            uint4 v = bq[i];
            *(uint4*)((sec ? ks : qs) + t * 40 + ch * 8) = v;
        }
    }
    {
        const __half2* bv = (const __half2*)(base + 2 * T * DH);
        for (int i = tid; i < 784; i += 256) {
            int t = i >> 4, d2 = i & 15;
            __half2 v = bv[i];
            vT[(d2 * 2)     * 72 + t] = __low2half(v);
            vT[(d2 * 2 + 1) * 72 + t] = __high2half(v);
        }
    }
    if (tid < 49) {
        int win = bn & 63;
        int wr = win >> 3, wc = win & 7;
        int tr = (tid * 37) >> 8, tc = tid - tr * 7;
        int h = wr * WS + tr, w = wc * WS + tc;
        int rh = (h < 49) ? 0 : ((h < 53) ? 1 : 2);
        int rw = (w < 49) ? 0 : ((w < 53) ? 1 : 2);
        rid[tid] = rh * 3 + rw;
    }
    __syncthreads();

    // ---- QK^T + fused exp/row-sum: warp (mt = wid>>1, ng = wid&1) ----
    {
        const int mt = wid >> 1, ng = wid & 1;
        const uint32_t uq = smem_u32(qs), uk = smem_u32(ks);
        uint32_t a[2][4];
        #pragma unroll
        for (int k2 = 0; k2 < 2; k2++) {
            uint32_t addr = uq + (uint32_t)((mt*16 + (lane & 15)) * 80
                                            + ((lane >> 4) * 8 + k2 * 16) * 2);
            ldsm_x4(a[k2][0], a[k2][1], a[k2][2], a[k2][3], addr);
        }
        uint32_t b[2][8];
        #pragma unroll
        for (int k2 = 0; k2 < 2; k2++)
            #pragma unroll
            for (int nt2 = 0; nt2 < 2; nt2++) {
                int rowB = ng*32 + nt2*16 + (lane & 7) + (((lane >> 4) & 1) << 3);
                uint32_t addr = uk + (uint32_t)(rowB * 80
                                                + (((lane >> 3) & 1) * 8 + k2 * 16) * 2);
                ldsm_x4(b[k2][nt2*4+0], b[k2][nt2*4+1], b[k2][nt2*4+2], b[k2][nt2*4+3], addr);
            }
        float c[4][4];
        #pragma unroll
        for (int j = 0; j < 4; j++)
            #pragma unroll
            for (int e = 0; e < 4; e++) c[j][e] = 0.f;
        #pragma unroll
        for (int j = 0; j < 4; j++) {
            mma_f16(c[j], a[0], b[0][j*2+0], b[0][j*2+1]);
            mma_f16(c[j], a[1], b[1][j*2+0], b[1][j*2+1]);
        }
        // fragment -> exp -> Pp (full 64x64 coverage incl. zero padding) + row sums
        #pragma unroll
        for (int hf = 0; hf < 2; hf++) {
            int t = mt*16 + (lane >> 2) + hf*8;
            bool tv = (t < 49);
            int tr = 0, tc = 0, rt = 0;
            if (tv) { tr = (t * 37) >> 8; tc = t - tr * 7; rt = rid[t]; }
            float rs = 0.f;
            #pragma unroll
            for (int j = 0; j < 4; j++) {
                float ev[2];
                #pragma unroll
                for (int e = 0; e < 2; e++) {
                    int s = ng*32 + j*8 + (lane & 3)*2 + e;
                    float v = 0.f;
                    if (tv && s < 49) {
                        int sr = (s * 37) >> 8, sc = s - sr * 7;
                        float val = c[j][hf*2+e] * SCALE
                            + __ldg(&table[((tr - sr + 6)*13 + (tc - sc + 6)) * NH + head]);
                        if (rt != rid[s]) val -= 100.0f;
                        v = __expf(val);
                    }
                    ev[e] = v;
                    rs += v;
                }
                int s0i = ng*32 + j*8 + (lane & 3)*2;
                *(__half2*)(Pp + t*72 + s0i) = __floats2half2_rn(ev[0], ev[1]);
            }
            rs += __shfl_xor_sync(0xFFFFFFFFu, rs, 1);
            rs += __shfl_xor_sync(0xFFFFFFFFu, rs, 2);
            if ((lane & 3) == 0) rsum[ng][t] = rs;
        }
    }
    __syncthreads();

    // ---- PV: warp (mt = wid>>1, nh2 = wid&1); out tile 16x16 per warp ----
    {
        const int mt = wid >> 1, nh2 = wid & 1;
        const uint32_t up = smem_u32(Pp), uv = smem_u32(vT);
        float c[2][4];
        #pragma unroll
        for (int j = 0; j < 2; j++)
            #pragma unroll
            for (int e = 0; e < 4; e++) c[j][e] = 0.f;
        #pragma unroll
        for (int k2 = 0; k2 < 4; k2++) {
            uint32_t a4[4];
            uint32_t aaddr = up + (uint32_t)((mt*16 + (lane & 15)) * 144
                                             + ((lane >> 4) * 8 + k2 * 16) * 2);
            ldsm_x4(a4[0], a4[1], a4[2], a4[3], aaddr);
            uint32_t b4[4];
            int rowB = nh2*16 + (lane & 7) + (((lane >> 4) & 1) << 3);
            uint32_t baddr = uv + (uint32_t)(rowB * 144
                                             + (((lane >> 3) & 1) * 8 + k2 * 16) * 2);
            ldsm_x4(b4[0], b4[1], b4[2], b4[3], baddr);
            mma_f16(c[0], a4, b4[0], b4[1]);
            mma_f16(c[1], a4, b4[2], b4[3]);
        }
        #pragma unroll
        for (int j = 0; j < 2; j++)
            #pragma unroll
            for (int hf = 0; hf < 2; hf++) {
                int t = mt*16 + (lane >> 2) + hf*8;
                if (t < 49) {
                    float inv = __frcp_rn(rsum[0][t] + rsum[1][t]);
                    int d0 = nh2*16 + j*8 + (lane & 3)*2;
                    size_t o = (size_t)(bn * T + t) * CDIM + head * DH + d0;
                    *(__half2*)(g_att16 + o) =
                        __floats2half2_rn(c[j][hf*2+0] * inv, c[j][hf*2+1] * inv);
                }
            }
    }
}

// ---------------------------------------------------------------------------
extern "C" void kernel_launch(void* const* d_in, const int* in_sizes, int n_in,
                              void* d_out, int out_size)
{
    const float* x     = (const float*)d_in[0];
    const float* wqkv  = (const float*)d_in[1];
    const float* bqkv  = (const float*)d_in[2];
    const float* wproj = (const float*)d_in[3];
    const float* bproj = (const float*)d_in[4];
    const float* table = (const float*)d_in[5];
    float* out = (float*)d_out;

    cudaFuncSetAttribute(gemm_mma<0>, cudaFuncAttributeMaxDynamicSharedMemorySize, SMEM_DYN);
    cudaFuncSetAttribute(gemm_mma<1>, cudaFuncAttributeMaxDynamicSharedMemorySize, SMEM_DYN);

    __half *wq16, *wp16;
    cudaGetSymbolAddress((void**)&wq16, g_wq16);
    cudaGetSymbolAddress((void**)&wp16, g_wp16);

    gather_convert_x<<<(MROWS * (CDIM/4) + 255) / 256, 256>>>(x);
    convert_w<<<(NQKV * CDIM / 4 + 255) / 256, 256>>>(wqkv,  wq16, NQKV * CDIM / 4);
    convert_w<<<(CDIM * CDIM / 4 + 255) / 256, 256>>>(wproj, wp16, CDIM * CDIM / 4);

    dim3 g1(NQKV / 128, MROWS / 128);     // (9, 784)
    gemm_mma<0><<<g1, 256, SMEM_DYN>>>(bqkv, nullptr);

    attn_kernel<<<BN * NH, 256>>>(table);

    dim3 g2(CDIM / 128, MROWS / 128);     // (3, 784)
    gemm_mma<1><<<g2, 256, SMEM_DYN>>>(bproj, out);
}